// round 16
// baseline (speedup 1.0000x reference)
#include <cuda_runtime.h>
#include <math.h>

#define N_NODES   4608
#define NFEAT     512
#define F1        256
#define FADJ      64
#define NHEADS    4
#define DHID      64
#define ATT_OUT   256
#define MLP       512
#define TOTAL_CATS 3072
#define NC        1536
#define NEG_INF   (-9000000000000000.0f)
#define ALPHA     0.2f
#define BKT       16     // mh tensor k-tile
#define BKS       32     // single-head k-tile
#define KHALF     2304   // split-K half for single head

// ---------------- scratch ----------------
__device__ float g_x1[N_NODES * F1];
__device__ float g_naf[N_NODES * FADJ];
__device__ float g_sim[(size_t)N_NODES * N_NODES];
__device__ float g_rinv[N_NODES];
__device__ float g_bcat[F1 * F1];
__device__ float g_whcat[N_NODES * F1];
__device__ float g_f1[NHEADS * N_NODES];
__device__ float g_f2[NHEADS * N_NODES];
__device__ float g_x2[N_NODES * F1];
__device__ float g_wh2[N_NODES * F1];
__device__ float g_f1o[N_NODES];
__device__ float g_f2o[N_NODES];
__device__ float g_x3[NC * F1];
__device__ float g_acc1[2 * NC * ATT_OUT];
__device__ float g_ssum1[2 * NC];

__device__ __forceinline__ float eluf(float v) { return v > 0.0f ? v : expm1f(v); }

__device__ __forceinline__ float fexp(float x)
{
    float t = x * 1.44269504088896340736f;
    float n = rintf(t);
    float f = t - n;
    float p = 1.33335581464284e-3f;
    p = fmaf(p, f, 9.61812910762848e-3f);
    p = fmaf(p, f, 5.55041086648216e-2f);
    p = fmaf(p, f, 2.40226506959101e-1f);
    p = fmaf(p, f, 6.93147180559945e-1f);
    p = fmaf(p, f, 1.0f);
    int ni = (int)n;
    return __int_as_float((ni + 127) << 23) * p;
}

__device__ __forceinline__ unsigned f2tf32(float f)
{
    unsigned r;
    asm("cvt.rna.tf32.f32 %0, %1;" : "=r"(r) : "f"(f));
    return r;
}

__device__ __forceinline__ void mma_tf32(float c[4], const unsigned a[4], const unsigned b[2])
{
    asm volatile(
        "mma.sync.aligned.m16n8k8.row.col.f32.tf32.tf32.f32 "
        "{%0,%1,%2,%3}, {%4,%5,%6,%7}, {%8,%9}, {%0,%1,%2,%3};"
        : "+f"(c[0]), "+f"(c[1]), "+f"(c[2]), "+f"(c[3])
        : "r"(a[0]), "r"(a[1]), "r"(a[2]), "r"(a[3]), "r"(b[0]), "r"(b[1]));
}

// ---------------- generic tiled SGEMM ----------------
template<int BM, int BN, int BK, int TM, int TN, int MODE>
__global__ void sgemm(const float* __restrict__ A, int lda,
                      const float* __restrict__ B, int ldb,
                      float* __restrict__ C, int ldc,
                      int M, int N, int K,
                      const float* __restrict__ bias,
                      const float* __restrict__ rowS,
                      const float* __restrict__ addmat, int ldadd)
{
    constexpr int NTX = BN / TN;
    constexpr int THREADS = (BM / TM) * (BN / TN);
    static_assert(THREADS == 256, "expect 256 threads");
    __shared__ float As[BK][BM];
    __shared__ float Bs[BK][BN];
    int tid = threadIdx.x;
    int bx = blockIdx.x * BN;
    int by = blockIdx.y * BM;
    int tx = tid % NTX, ty = tid / NTX;
    float acc[TM][TN];
#pragma unroll
    for (int i = 0; i < TM; i++)
#pragma unroll
        for (int j = 0; j < TN; j++) acc[i][j] = 0.0f;

    for (int k0 = 0; k0 < K; k0 += BK) {
#pragma unroll
        for (int i = tid * 4; i < BM * BK; i += THREADS * 4) {
            int r = i / BK, c = i % BK;
            float4 v = *(const float4*)(A + (size_t)(by + r) * lda + k0 + c);
            As[c + 0][r] = v.x; As[c + 1][r] = v.y;
            As[c + 2][r] = v.z; As[c + 3][r] = v.w;
        }
#pragma unroll
        for (int i = tid * 4; i < BK * BN; i += THREADS * 4) {
            int r = i / BN, c = i % BN;
            *(float4*)(&Bs[r][c]) = *(const float4*)(B + (size_t)(k0 + r) * ldb + bx + c);
        }
        __syncthreads();
#pragma unroll
        for (int kk = 0; kk < BK; kk++) {
            float ra[TM], rb[TN];
#pragma unroll
            for (int i = 0; i < TM; i++) ra[i] = As[kk][ty * TM + i];
#pragma unroll
            for (int j = 0; j < TN; j++) rb[j] = Bs[kk][tx * TN + j];
#pragma unroll
            for (int i = 0; i < TM; i++)
#pragma unroll
                for (int j = 0; j < TN; j++) acc[i][j] += ra[i] * rb[j];
        }
        __syncthreads();
    }

#pragma unroll
    for (int i = 0; i < TM; i++) {
        int r = by + ty * TM + i;
#pragma unroll
        for (int j = 0; j < TN; j++) {
            int c = bx + tx * TN + j;
            float v = acc[i][j];
            if (MODE == 0) {
                if (bias) v += bias[c];
            }
            C[(size_t)r * ldc + c] = v;
        }
    }
}

// ---------------- sim = naf @ naf^T — LOCKED math, float4 stores ----------------
__global__ void gemm_nt_sim()
{
    __shared__ float Asm[64][65];
    __shared__ float Bsm[64][65];
    int by = blockIdx.y * 64, bx = blockIdx.x * 64;
    int tid = threadIdx.x;
#pragma unroll
    for (int i = tid * 4; i < 64 * 64; i += 256 * 4) {
        int r = i >> 6, c = i & 63;
        float4 a = *(const float4*)&g_naf[(size_t)(by + r) * 64 + c];
        Asm[r][c + 0] = a.x; Asm[r][c + 1] = a.y; Asm[r][c + 2] = a.z; Asm[r][c + 3] = a.w;
        float4 b = *(const float4*)&g_naf[(size_t)(bx + r) * 64 + c];
        Bsm[r][c + 0] = b.x; Bsm[r][c + 1] = b.y; Bsm[r][c + 2] = b.z; Bsm[r][c + 3] = b.w;
    }
    __syncthreads();
    int tx = tid & 15, ty = tid >> 4;
    float acc[4][4];
#pragma unroll
    for (int i = 0; i < 4; i++)
#pragma unroll
        for (int j = 0; j < 4; j++) acc[i][j] = 0.0f;
#pragma unroll
    for (int k = 0; k < 64; k++) {
        float ra[4], rb[4];
#pragma unroll
        for (int i = 0; i < 4; i++) ra[i] = Asm[ty * 4 + i][k];
#pragma unroll
        for (int j = 0; j < 4; j++) rb[j] = Bsm[tx * 4 + j][k];
#pragma unroll
        for (int i = 0; i < 4; i++)
#pragma unroll
            for (int j = 0; j < 4; j++) acc[i][j] += ra[i] * rb[j];
    }
#pragma unroll
    for (int i = 0; i < 4; i++) {
        float4 o = make_float4(acc[i][0], acc[i][1], acc[i][2], acc[i][3]);
        *(float4*)&g_sim[(size_t)(by + ty * 4 + i) * N_NODES + bx + tx * 4] = o;
    }
}

// ---------------- row norm — LOCKED ----------------
__global__ void norm_rows()
{
    int n = blockIdx.x, t = threadIdx.x;  // 64 threads
    float v = g_naf[(size_t)n * 64 + t];
    float ss = v * v;
    for (int o = 16; o > 0; o >>= 1) ss += __shfl_down_sync(0xffffffffu, ss, o);
    __shared__ float sm[2];
    if ((t & 31) == 0) sm[t >> 5] = ss;
    __syncthreads();
    float nrm = sqrtf(sm[0] + sm[1]);
    g_naf[(size_t)n * 64 + t] = v / fmaxf(nrm, 1e-12f);
}

// ---------------- rowsum block 1 — LOCKED ----------------
__global__ void rowsum_kernel()
{
    int n = blockIdx.x, tid = threadIdx.x;
    const float* row = g_sim + (size_t)n * N_NODES;
    float s = 0.0f;
    for (int m = tid; m < N_NODES; m += 256) s += row[m];
    __shared__ float sm[256];
    sm[tid] = s; __syncthreads();
    for (int st = 128; st > 0; st >>= 1) {
        if (tid < st) sm[tid] += sm[tid + st];
        __syncthreads();
    }
    if (tid == 0) {
        float r = 1.0f / sm[0];
        g_rinv[n] = isinf(r) ? 0.0f : r;
    }
}

// ---------------- rowsum rows >= 1536 — LOCKED ----------------
__global__ void rowsum_kernel_f64(int base)
{
    int n = base + blockIdx.x, tid = threadIdx.x;
    const float* row = g_sim + (size_t)n * N_NODES;
    double s = 0.0;
    for (int m = tid; m < N_NODES; m += 256) s += (double)row[m];
    __shared__ double sm[256];
    sm[tid] = s; __syncthreads();
    for (int st = 128; st > 0; st >>= 1) {
        if (tid < st) sm[tid] += sm[tid + st];
        __syncthreads();
    }
    if (tid == 0) {
        float rs = (float)sm[0];
        float r = 1.0f / rs;
        g_rinv[n] = isinf(r) ? 0.0f : r;
    }
}

__global__ void relu_inplace(float* p, int n)
{
    int i = blockIdx.x * 256 + threadIdx.x;
    if (i < n) p[i] = fmaxf(p[i], 0.0f);
}

__global__ void repack_wheads(const float* __restrict__ W)
{
    int i = blockIdx.x * 256 + threadIdx.x;
    if (i < NHEADS * F1 * DHID) {
        int h = i >> 14;
        int f = (i >> 6) & 255;
        int d = i & 63;
        g_bcat[f * 256 + h * 64 + d] = W[i];
    }
}

__global__ void f12_mh(const float* __restrict__ a_heads)
{
    int n = blockIdx.x;
    int h = threadIdx.x >> 5, l = threadIdx.x & 31;
    const float* wr = g_whcat + (size_t)n * 256 + h * 64;
    const float* a = a_heads + h * 128;
    float x0 = wr[l], x1 = wr[l + 32];
    float s1 = x0 * a[l] + x1 * a[l + 32];
    float s2 = x0 * a[64 + l] + x1 * a[96 + l];
    for (int o = 16; o > 0; o >>= 1) {
        s1 += __shfl_down_sync(0xffffffffu, s1, o);
        s2 += __shfl_down_sync(0xffffffffu, s2, o);
    }
    if (l == 0) { g_f1[h * N_NODES + n] = s1; g_f2[h * N_NODES + n] = s2; }
}

__global__ void f12_single(const float* __restrict__ a_out)
{
    int n = blockIdx.x, t = threadIdx.x;
    float xv = g_wh2[(size_t)n * 256 + t];
    __shared__ float sm1[256], sm2[256];
    sm1[t] = xv * a_out[t];
    sm2[t] = xv * a_out[256 + t];
    __syncthreads();
    for (int st = 128; st > 0; st >>= 1) {
        if (t < st) { sm1[t] += sm1[t + st]; sm2[t] += sm2[t + st]; }
        __syncthreads();
    }
    if (t == 0) { g_f1o[n] = sm1[0]; g_f2o[n] = sm2[0]; }
}

// ---------------- fused flash-GAT multihead — 3xTF32 tensor cores ----------------
// grid (NHEADS, N_NODES/128), block 256 = 8 warps (4 m-warps x 2 n-warps; warp tile 32x32).
// acc += pHi*wHi + pLo*wHi + pHi*wLo  (3xTF32: ~fp32 precision, only affects x2 -> output 0).
__global__ void fused_gat_mh_tc()
{
    int h = blockIdx.x;
    int by = blockIdx.y * 128;
    int tid = threadIdx.x;
    int lane = tid & 31;
    int warp = tid >> 5;
    int wm = warp & 3;        // m-warp: rows wm*32..+31
    int wn = warp >> 2;       // n-warp: cols wn*32..+31
    int g = lane >> 2;        // group 0..7
    int tg = lane & 3;        // thread-in-group 0..3

    // strides chosen so fragment LDS banks = 8*tg + g (+const) -> conflict-free
    __shared__ float PsHi[BKT][136], PsLo[BKT][136];
    __shared__ float WsHi[BKT][72],  WsLo[BKT][72];
    __shared__ float f1s[128], rinvs[128], ssum_s[128];

    if (tid < 128) {
        f1s[tid]   = g_f1[h * N_NODES + by + tid];
        rinvs[tid] = g_rinv[by + tid];
    }
    __syncthreads();

    float c[2][4][4];
#pragma unroll
    for (int ma = 0; ma < 2; ma++)
#pragma unroll
        for (int na = 0; na < 4; na++)
#pragma unroll
            for (int q = 0; q < 4; q++) c[ma][na][q] = 0.0f;
    float row_sum = 0.0f;

    for (int m0 = 0; m0 < N_NODES; m0 += BKT) {
        // generate P tile (16 k x 128 r), k-fast for coalesced sim reads
#pragma unroll
        for (int i = 0; i < 8; i++) {
            int idx = tid + i * 256;
            int r = idx >> 4, k = idx & 15;
            float s = g_sim[(size_t)(by + r) * N_NODES + m0 + k];
            bool mask = (rinvs[r] * s) > 0.0f;
            float e = f1s[r] + g_f2[h * N_NODES + m0 + k];
            e = e > 0.0f ? e : ALPHA * e;
            float p = mask ? fexp(e) : 0.0f;
            unsigned hb = f2tf32(p);
            float hf = __uint_as_float(hb);
            PsHi[k][r] = hf;
            PsLo[k][r] = __uint_as_float(f2tf32(__fsub_rn(p, hf)));
        }
        // Wh tile (16 k x 64 c)
#pragma unroll
        for (int i = 0; i < 4; i++) {
            int idx = tid + i * 256;
            int k = idx >> 6, cc = idx & 63;
            float w = g_whcat[(size_t)(m0 + k) * F1 + h * 64 + cc];
            unsigned hb = f2tf32(w);
            float hf = __uint_as_float(hb);
            WsHi[k][cc] = hf;
            WsLo[k][cc] = __uint_as_float(f2tf32(__fsub_rn(w, hf)));
        }
        __syncthreads();

#pragma unroll
        for (int ka = 0; ka < BKT / 8; ka++) {
            int kb = ka * 8;
            unsigned aHi[2][4], aLo[2][4];
#pragma unroll
            for (int ma = 0; ma < 2; ma++) {
                int r0 = wm * 32 + ma * 16 + g;
                int k0 = kb + tg;
                aHi[ma][0] = __float_as_uint(PsHi[k0][r0]);
                aHi[ma][1] = __float_as_uint(PsHi[k0][r0 + 8]);
                aHi[ma][2] = __float_as_uint(PsHi[k0 + 4][r0]);
                aHi[ma][3] = __float_as_uint(PsHi[k0 + 4][r0 + 8]);
                aLo[ma][0] = __float_as_uint(PsLo[k0][r0]);
                aLo[ma][1] = __float_as_uint(PsLo[k0][r0 + 8]);
                aLo[ma][2] = __float_as_uint(PsLo[k0 + 4][r0]);
                aLo[ma][3] = __float_as_uint(PsLo[k0 + 4][r0 + 8]);
            }
            unsigned bHi[4][2], bLo[4][2];
#pragma unroll
            for (int na = 0; na < 4; na++) {
                int cn = wn * 32 + na * 8 + g;
                int k0 = kb + tg;
                bHi[na][0] = __float_as_uint(WsHi[k0][cn]);
                bHi[na][1] = __float_as_uint(WsHi[k0 + 4][cn]);
                bLo[na][0] = __float_as_uint(WsLo[k0][cn]);
                bLo[na][1] = __float_as_uint(WsLo[k0 + 4][cn]);
            }
#pragma unroll
            for (int ma = 0; ma < 2; ma++)
#pragma unroll
                for (int na = 0; na < 4; na++) {
                    mma_tf32(c[ma][na], aHi[ma], bHi[na]);
                    mma_tf32(c[ma][na], aLo[ma], bHi[na]);
                    mma_tf32(c[ma][na], aHi[ma], bLo[na]);
                }
        }
        // row sums from hi+lo (<=1e-7 deviation; feeds output 0 only)
        if (tid < 128) {
#pragma unroll
            for (int k = 0; k < BKT; k++)
                row_sum += PsHi[k][tid] + PsLo[k][tid];
        }
        __syncthreads();
    }

    if (tid < 128) ssum_s[tid] = row_sum;
    __syncthreads();

#pragma unroll
    for (int ma = 0; ma < 2; ma++) {
        int rl0 = wm * 32 + ma * 16 + g;
#pragma unroll
        for (int na = 0; na < 4; na++) {
            int cc = h * 64 + wn * 32 + na * 8 + tg * 2;
            {
                float sd = ssum_s[rl0];
                size_t base = (size_t)(by + rl0) * F1 + cc;
                g_x2[base]     = eluf(c[ma][na][0] / sd) + g_x1[base];
                g_x2[base + 1] = eluf(c[ma][na][1] / sd) + g_x1[base + 1];
            }
            {
                float sd = ssum_s[rl0 + 8];
                size_t base = (size_t)(by + rl0 + 8) * F1 + cc;
                g_x2[base]     = eluf(c[ma][na][2] / sd) + g_x1[base];
                g_x2[base + 1] = eluf(c[ma][na][3] / sd) + g_x1[base + 1];
            }
        }
    }
}

// ---------------- fused flash-GAT single head (split-K=2) ----------------
__global__ void fused_gat_single()
{
    int bx = blockIdx.x * 64;
    int byl = blockIdx.y * 64;
    int by = TOTAL_CATS + byl;
    int z = blockIdx.z;
    int m_base = z * KHALF;
    int tid = threadIdx.x;
    int tx = tid & 15;
    int ty = tid >> 4;

    __shared__ float Ps[BKS][68];
    __shared__ float Ws[BKS][68];
    __shared__ float f1s[64], rinvs[64];

    if (tid < 64) {
        f1s[tid]   = g_f1o[by + tid];
        rinvs[tid] = g_rinv[by + tid];
    }

    float acc[4][4];
#pragma unroll
    for (int i = 0; i < 4; i++)
#pragma unroll
        for (int j = 0; j < 4; j++) acc[i][j] = 0.0f;
    float row_sum = 0.0f;
    __syncthreads();

    for (int m0 = m_base; m0 < m_base + KHALF; m0 += BKS) {
#pragma unroll
        for (int i = tid; i < BKS * 16; i += 256) {
            int k = i >> 4, c = (i & 15) * 4;
            *(float4*)&Ws[k][c] =
                *(const float4*)&g_wh2[(size_t)(m0 + k) * ATT_OUT + bx + c];
        }
#pragma unroll
        for (int i = 0; i < 8; i++) {
            int idx = tid + i * 256;
            int r = idx >> 5, k = idx & 31;
            float s = g_sim[(size_t)(by + r) * N_NODES + m0 + k];
            bool mask = (rinvs[r] * s) > 0.0f;
            float e = f1s[r] + g_f2o[m0 + k];
            e = e > 0.0f ? e : ALPHA * e;
            Ps[k][r] = mask ? fexp(e) : 0.0f;
        }
        __syncthreads();
#pragma unroll
        for (int kk = 0; kk < BKS; kk++) {
            float4 a0 = *(float4*)&Ps[kk][ty * 4];
            float4 b0 = *(float4*)&Ws[kk][tx * 4];
            float ra[4] = {a0.x, a0.y, a0.z, a0.w};
            float rb[4] = {b0.x, b0.y, b0.z, b0.w};
#pragma unroll
            for (int i = 0; i < 4; i++)
#pragma unroll
                for (int j = 0; j < 4; j++) acc[i][j] += ra[i] * rb[j];
        }
        if (tid < 64) {
#pragma unroll
            for (int k = 0; k < BKS; k++) row_sum += Ps[k][tid];
        }
        __syncthreads();
    }

    float* accout = g_acc1 + (size_t)z * NC * ATT_OUT;
#pragma unroll
    for (int i = 0; i < 4; i++) {
        int rl = byl + ty * 4 + i;
#pragma unroll
        for (int j = 0; j < 4; j++)
            accout[(size_t)rl * ATT_OUT + bx + tx * 4 + j] = acc[i][j];
    }
    if (blockIdx.x == 0 && tid < 64)
        g_ssum1[z * NC + byl + tid] = row_sum;
}

__global__ void combine_single()
{
    int i = blockIdx.x * 256 + threadIdx.x;
    int r = i >> 8;
    int c = i & 255;
    float a = g_acc1[i] + g_acc1[NC * ATT_OUT + i];
    float s = g_ssum1[r] + g_ssum1[NC + r];
    g_x3[i] = eluf(a / s + g_x2[(size_t)(TOTAL_CATS + r) * F1 + c]);
}

// ---------------- bipartite-graph column softmax — LOCKED ----------------
__global__ void bgs_kernel(float* __restrict__ out)
{
    int ds = blockIdx.y;
    int tx = threadIdx.x, ty = threadIdx.y;
    int jloc = blockIdx.x * 32 + tx;
    int col = TOTAL_CATS + jloc;
    int base = ds * NC;
    __shared__ float red[8][33];

    float mx = -3.4e38f;
    for (int i = ty; i < NC; i += 8) {
        float v = (g_rinv[base + i] * g_sim[(size_t)(base + i) * N_NODES + col]) / 0.05f;
        mx = fmaxf(mx, v);
    }
    red[ty][tx] = mx; __syncthreads();
    if (ty == 0) {
        float m = red[0][tx];
        for (int k = 1; k < 8; k++) m = fmaxf(m, red[k][tx]);
        red[0][tx] = m;
    }
    __syncthreads();
    mx = red[0][tx];
    __syncthreads();

    float s = 0.0f;
    for (int i = ty; i < NC; i += 8) {
        float v = (g_rinv[base + i] * g_sim[(size_t)(base + i) * N_NODES + col]) / 0.05f;
        s += __expf(v - mx);
    }
    red[ty][tx] = s; __syncthreads();
    if (ty == 0) {
        float t2 = 0.0f;
        for (int k = 0; k < 8; k++) t2 += red[k][tx];
        red[0][tx] = t2;
    }
    __syncthreads();
    float inv = 1.0f / red[0][tx];

    float* o = out + NC * MLP + (size_t)ds * NC * NC;
    for (int i = ty; i < NC; i += 8) {
        float v = (g_rinv[base + i] * g_sim[(size_t)(base + i) * N_NODES + col]) / 0.05f;
        o[(size_t)i * NC + jloc] = __expf(v - mx) * inv;
    }
}

// ---------------- launch (single stream) ----------------
extern "C" void kernel_launch(void* const* d_in, const int* in_sizes, int n_in,
                              void* d_out, int out_size)
{
    const float* x        = (const float*)d_in[0];
    const float* W_before = (const float*)d_in[1];
    const float* b_before = (const float*)d_in[2];
    const float* W_adj    = (const float*)d_in[3];
    const float* b_adj    = (const float*)d_in[4];
    const float* W_heads  = (const float*)d_in[5];
    const float* a_heads  = (const float*)d_in[6];
    const float* W_out    = (const float*)d_in[7];
    const float* a_out    = (const float*)d_in[8];
    const float* W_lin1   = (const float*)d_in[9];
    const float* b_lin1   = (const float*)d_in[10];
    float* out = (float*)d_out;

    float *p_x1, *p_naf, *p_whcat, *p_x2, *p_wh2, *p_x3, *p_bcat;
    cudaGetSymbolAddress((void**)&p_x1, g_x1);
    cudaGetSymbolAddress((void**)&p_naf, g_naf);
    cudaGetSymbolAddress((void**)&p_whcat, g_whcat);
    cudaGetSymbolAddress((void**)&p_x2, g_x2);
    cudaGetSymbolAddress((void**)&p_wh2, g_wh2);
    cudaGetSymbolAddress((void**)&p_x3, g_x3);
    cudaGetSymbolAddress((void**)&p_bcat, g_bcat);

    // 1. x1 = x @ W_before + b_before
    sgemm<128, 64, 16, 8, 4, 0><<<dim3(F1 / 64, N_NODES / 128), 256>>>(
        x, NFEAT, W_before, F1, p_x1, F1, N_NODES, F1, NFEAT, b_before, nullptr, nullptr, 0);

    // 2. af = x1 @ W_adj + b_adj — LOCKED params
    sgemm<64, 64, 16, 4, 4, 0><<<dim3(1, N_NODES / 64), 256>>>(
        p_x1, F1, W_adj, FADJ, p_naf, FADJ, N_NODES, FADJ, F1, b_adj, nullptr, nullptr, 0);

    // 3. normalize rows — LOCKED
    norm_rows<<<N_NODES, 64>>>();

    // 4. sim = naf @ naf^T — LOCKED math
    gemm_nt_sim<<<dim3(N_NODES / 64, N_NODES / 64), 256>>>();

    // 5. r_inv — LOCKED
    rowsum_kernel<<<NC, 256>>>();
    rowsum_kernel_f64<<<N_NODES - NC, 256>>>(NC);

    // 6. x1 = relu(x1)
    relu_inplace<<<(N_NODES * F1 + 255) / 256, 256>>>(p_x1, N_NODES * F1);

    // 7. repack W_heads
    repack_wheads<<<(NHEADS * F1 * DHID + 255) / 256, 256>>>(W_heads);

    // 8. whcat = relu(x1) @ bcat
    sgemm<128, 64, 16, 8, 4, 0><<<dim3(F1 / 64, N_NODES / 128), 256>>>(
        p_x1, F1, p_bcat, F1, p_whcat, F1, N_NODES, F1, F1, nullptr, nullptr, nullptr, 0);

    // 9. f1/f2 per head
    f12_mh<<<N_NODES, 128>>>(a_heads);

    // 10. fused multihead attention — 3xTF32 tensor cores
    fused_gat_mh_tc<<<dim3(NHEADS, N_NODES / 128), 256>>>();

    // 11. wh2 = x2 @ W_out
    sgemm<128, 64, 16, 8, 4, 0><<<dim3(ATT_OUT / 64, N_NODES / 128), 256>>>(
        p_x2, F1, W_out, ATT_OUT, p_wh2, ATT_OUT, N_NODES, ATT_OUT, F1, nullptr, nullptr, nullptr, 0);

    // 12. f1o/f2o
    f12_single<<<N_NODES, 256>>>(a_out);

    // 13. fused single-head attention (split-K=2) + combine
    fused_gat_single<<<dim3(ATT_OUT / 64, NC / 64, 2), 256>>>();
    combine_single<<<NC * ATT_OUT / 256, 256>>>();

    // 14. feat_mlp tail = x3 @ W_lin1 + b_lin1
    sgemm<128, 64, 16, 8, 4, 0><<<dim3(MLP / 64, NC / 128), 256>>>(
        p_x3, ATT_OUT, W_lin1, MLP, out, MLP, NC, MLP, ATT_OUT, b_lin1, nullptr, nullptr, 0);

    // 15. bipartite column softmaxes — LOCKED
    bgs_kernel<<<dim3(NC / 32, 2), dim3(32, 8)>>>(out);
}

// round 17
// speedup vs baseline: 1.3509x; 1.3509x over previous
#include <cuda_runtime.h>
#include <math.h>

#define N_NODES   4608
#define NFEAT     512
#define F1        256
#define FADJ      64
#define NHEADS    4
#define DHID      64
#define ATT_OUT   256
#define MLP       512
#define TOTAL_CATS 3072
#define NC        1536
#define NEG_INF   (-9000000000000000.0f)
#define ALPHA     0.2f
#define BKM       16     // mh k-tile (double buffered)
#define BKS       32     // single-head k-tile (double buffered)
#define KHALF     2304   // split-K half for single head

// ---------------- scratch ----------------
__device__ float g_x1[N_NODES * F1];      // raw x1 (locked af chain reads this)
__device__ float g_x1r[N_NODES * F1];     // relu(x1)
__device__ float g_naf[N_NODES * FADJ];
__device__ float g_sim[(size_t)N_NODES * N_NODES];
__device__ float g_rinv[N_NODES];
__device__ float g_bcat[F1 * F1];
__device__ float g_whcat[N_NODES * F1];
__device__ float g_f1[NHEADS * N_NODES];
__device__ float g_f2[NHEADS * N_NODES];
__device__ float g_x2[N_NODES * F1];
__device__ float g_wh2[N_NODES * F1];
__device__ float g_f1o[N_NODES];
__device__ float g_f2o[N_NODES];
__device__ float g_x3[NC * F1];
__device__ float g_acc1[2 * NC * ATT_OUT];
__device__ float g_ssum1[2 * NC];

__device__ __forceinline__ float eluf(float v) { return v > 0.0f ? v : expm1f(v); }

// ---------------- generic tiled SGEMM (ascending-k fma chain) ----------------
// MODE 0: C = acc + (bias? bias[c] : 0); optionally also write relu to Crelu.
template<int BM, int BN, int BK, int TM, int TN, int MODE>
__global__ void sgemm(const float* __restrict__ A, int lda,
                      const float* __restrict__ B, int ldb,
                      float* __restrict__ C, int ldc,
                      int M, int N, int K,
                      const float* __restrict__ bias,
                      float* __restrict__ Crelu)
{
    constexpr int NTX = BN / TN;
    constexpr int THREADS = (BM / TM) * (BN / TN);
    static_assert(THREADS == 256, "expect 256 threads");
    __shared__ float As[BK][BM];
    __shared__ float Bs[BK][BN];
    int tid = threadIdx.x;
    int bx = blockIdx.x * BN;
    int by = blockIdx.y * BM;
    int tx = tid % NTX, ty = tid / NTX;
    float acc[TM][TN];
#pragma unroll
    for (int i = 0; i < TM; i++)
#pragma unroll
        for (int j = 0; j < TN; j++) acc[i][j] = 0.0f;

    for (int k0 = 0; k0 < K; k0 += BK) {
#pragma unroll
        for (int i = tid * 4; i < BM * BK; i += THREADS * 4) {
            int r = i / BK, c = i % BK;
            float4 v = *(const float4*)(A + (size_t)(by + r) * lda + k0 + c);
            As[c + 0][r] = v.x; As[c + 1][r] = v.y;
            As[c + 2][r] = v.z; As[c + 3][r] = v.w;
        }
#pragma unroll
        for (int i = tid * 4; i < BK * BN; i += THREADS * 4) {
            int r = i / BN, c = i % BN;
            *(float4*)(&Bs[r][c]) = *(const float4*)(B + (size_t)(k0 + r) * ldb + bx + c);
        }
        __syncthreads();
#pragma unroll
        for (int kk = 0; kk < BK; kk++) {
            float ra[TM], rb[TN];
#pragma unroll
            for (int i = 0; i < TM; i++) ra[i] = As[kk][ty * TM + i];
#pragma unroll
            for (int j = 0; j < TN; j++) rb[j] = Bs[kk][tx * TN + j];
#pragma unroll
            for (int i = 0; i < TM; i++)
#pragma unroll
                for (int j = 0; j < TN; j++) acc[i][j] += ra[i] * rb[j];
        }
        __syncthreads();
    }

#pragma unroll
    for (int i = 0; i < TM; i++) {
        int r = by + ty * TM + i;
#pragma unroll
        for (int j = 0; j < TN; j++) {
            int c = bx + tx * TN + j;
            float v = acc[i][j];
            if (bias) v += bias[c];
            C[(size_t)r * ldc + c] = v;
            if (Crelu) Crelu[(size_t)r * ldc + c] = fmaxf(v, 0.0f);
        }
    }
}

// ---------------- sim = naf @ naf^T — LOCKED math, float4 stores ----------------
__global__ void gemm_nt_sim()
{
    __shared__ float Asm[64][65];
    __shared__ float Bsm[64][65];
    int by = blockIdx.y * 64, bx = blockIdx.x * 64;
    int tid = threadIdx.x;
#pragma unroll
    for (int i = tid * 4; i < 64 * 64; i += 256 * 4) {
        int r = i >> 6, c = i & 63;
        float4 a = *(const float4*)&g_naf[(size_t)(by + r) * 64 + c];
        Asm[r][c + 0] = a.x; Asm[r][c + 1] = a.y; Asm[r][c + 2] = a.z; Asm[r][c + 3] = a.w;
        float4 b = *(const float4*)&g_naf[(size_t)(bx + r) * 64 + c];
        Bsm[r][c + 0] = b.x; Bsm[r][c + 1] = b.y; Bsm[r][c + 2] = b.z; Bsm[r][c + 3] = b.w;
    }
    __syncthreads();
    int tx = tid & 15, ty = tid >> 4;
    float acc[4][4];
#pragma unroll
    for (int i = 0; i < 4; i++)
#pragma unroll
        for (int j = 0; j < 4; j++) acc[i][j] = 0.0f;
#pragma unroll
    for (int k = 0; k < 64; k++) {
        float ra[4], rb[4];
#pragma unroll
        for (int i = 0; i < 4; i++) ra[i] = Asm[ty * 4 + i][k];
#pragma unroll
        for (int j = 0; j < 4; j++) rb[j] = Bsm[tx * 4 + j][k];
#pragma unroll
        for (int i = 0; i < 4; i++)
#pragma unroll
            for (int j = 0; j < 4; j++) acc[i][j] += ra[i] * rb[j];
    }
#pragma unroll
    for (int i = 0; i < 4; i++) {
        float4 o = make_float4(acc[i][0], acc[i][1], acc[i][2], acc[i][3]);
        *(float4*)&g_sim[(size_t)(by + ty * 4 + i) * N_NODES + bx + tx * 4] = o;
    }
}

// ---------------- row norm — LOCKED ----------------
__global__ void norm_rows()
{
    int n = blockIdx.x, t = threadIdx.x;  // 64 threads
    float v = g_naf[(size_t)n * 64 + t];
    float ss = v * v;
    for (int o = 16; o > 0; o >>= 1) ss += __shfl_down_sync(0xffffffffu, ss, o);
    __shared__ float sm[2];
    if ((t & 31) == 0) sm[t >> 5] = ss;
    __syncthreads();
    float nrm = sqrtf(sm[0] + sm[1]);
    g_naf[(size_t)n * 64 + t] = v / fmaxf(nrm, 1e-12f);
}

// ---------------- rowsum (merged): rows <NC fp32 R1-order; rows >=NC fp64 — LOCKED math ----
__global__ void rowsum_all()
{
    int n = blockIdx.x, tid = threadIdx.x;
    const float* row = g_sim + (size_t)n * N_NODES;
    __shared__ float  sm[256];
    __shared__ double smd[256];
    if (n < NC) {
        float s = 0.0f;
        for (int m = tid; m < N_NODES; m += 256) s += row[m];
        sm[tid] = s; __syncthreads();
        for (int st = 128; st > 0; st >>= 1) {
            if (tid < st) sm[tid] += sm[tid + st];
            __syncthreads();
        }
        if (tid == 0) {
            float r = 1.0f / sm[0];
            g_rinv[n] = isinf(r) ? 0.0f : r;
        }
    } else {
        double s = 0.0;
        for (int m = tid; m < N_NODES; m += 256) s += (double)row[m];
        smd[tid] = s; __syncthreads();
        for (int st = 128; st > 0; st >>= 1) {
            if (tid < st) smd[tid] += smd[tid + st];
            __syncthreads();
        }
        if (tid == 0) {
            float rs = (float)smd[0];
            float r = 1.0f / rs;
            g_rinv[n] = isinf(r) ? 0.0f : r;
        }
    }
}

__global__ void repack_wheads(const float* __restrict__ W)
{
    int i = blockIdx.x * 256 + threadIdx.x;
    if (i < NHEADS * F1 * DHID) {
        int h = i >> 14;
        int f = (i >> 6) & 255;
        int d = i & 63;
        g_bcat[f * 256 + h * 64 + d] = W[i];
    }
}

__global__ void f12_mh(const float* __restrict__ a_heads)
{
    int n = blockIdx.x;
    int h = threadIdx.x >> 5, l = threadIdx.x & 31;
    const float* wr = g_whcat + (size_t)n * 256 + h * 64;
    const float* a = a_heads + h * 128;
    float x0 = wr[l], x1 = wr[l + 32];
    float s1 = x0 * a[l] + x1 * a[l + 32];
    float s2 = x0 * a[64 + l] + x1 * a[96 + l];
    for (int o = 16; o > 0; o >>= 1) {
        s1 += __shfl_down_sync(0xffffffffu, s1, o);
        s2 += __shfl_down_sync(0xffffffffu, s2, o);
    }
    if (l == 0) { g_f1[h * N_NODES + n] = s1; g_f2[h * N_NODES + n] = s2; }
}

__global__ void f12_single(const float* __restrict__ a_out)
{
    int n = blockIdx.x, t = threadIdx.x;
    float xv = g_wh2[(size_t)n * 256 + t];
    __shared__ float sm1[256], sm2[256];
    sm1[t] = xv * a_out[t];
    sm2[t] = xv * a_out[256 + t];
    __syncthreads();
    for (int st = 128; st > 0; st >>= 1) {
        if (t < st) { sm1[t] += sm1[t + st]; sm2[t] += sm2[t + st]; }
        __syncthreads();
    }
    if (t == 0) { g_f1o[n] = sm1[0]; g_f2o[n] = sm2[0]; }
}

// ---------------- fused flash-GAT multihead: 512 threads, double-buffered (R15) ----------------
__global__ void fused_gat_mh()
{
    int h = blockIdx.x;
    int by = blockIdx.y * 128;
    int tid = threadIdx.x;
    int tx = tid & 15;   // cols tx*4 .. +3   (64 cols)
    int ty = tid >> 4;   // rows ty*4 .. +3   (128 rows, 32 groups)

    __shared__ float Ps[2][BKM][132];
    __shared__ float Ws[2][BKM][68];
    __shared__ float f1s[128], rinvs[128], ssum_s[128];

    if (tid < 128) {
        f1s[tid]   = g_f1[h * N_NODES + by + tid];
        rinvs[tid] = g_rinv[by + tid];
    }
    __syncthreads();

    // tile 0 -> buffer 0
    {
        if (tid < 256) {
            int k = tid >> 4, c = (tid & 15) * 4;
            *(float4*)&Ws[0][k][c] = *(const float4*)&g_whcat[(size_t)k * F1 + h * 64 + c];
        }
#pragma unroll
        for (int i = 0; i < 4; i++) {
            int idx = tid + i * 512;
            int r = idx >> 4, kk = idx & 15;
            float s = g_sim[(size_t)(by + r) * N_NODES + kk];
            bool mask = (rinvs[r] * s) > 0.0f;
            float e = f1s[r] + g_f2[h * N_NODES + kk];
            e = e > 0.0f ? e : ALPHA * e;
            Ps[0][kk][r] = mask ? __expf(e) : 0.0f;
        }
    }
    __syncthreads();

    float acc[4][4];
#pragma unroll
    for (int i = 0; i < 4; i++)
#pragma unroll
        for (int j = 0; j < 4; j++) acc[i][j] = 0.0f;
    float row_sum = 0.0f;

    const int NT = N_NODES / BKM;   // 288
    for (int t = 0; t < NT; t++) {
        int cur = t & 1;
        int m1 = (t + 1) * BKM;
        float4 wreg;
        float sreg[4];
        if (t + 1 < NT) {
            if (tid < 256) {
                int k = tid >> 4, c = (tid & 15) * 4;
                wreg = *(const float4*)&g_whcat[(size_t)(m1 + k) * F1 + h * 64 + c];
            }
#pragma unroll
            for (int i = 0; i < 4; i++) {
                int idx = tid + i * 512;
                int r = idx >> 4, kk = idx & 15;
                sreg[i] = g_sim[(size_t)(by + r) * N_NODES + m1 + kk];
            }
        }
        // compute on buffer cur
#pragma unroll
        for (int kk = 0; kk < BKM; kk++) {
            float4 a0 = *(float4*)&Ps[cur][kk][ty * 4];
            float4 b0 = *(float4*)&Ws[cur][kk][tx * 4];
            float ra[4] = {a0.x, a0.y, a0.z, a0.w};
            float rb[4] = {b0.x, b0.y, b0.z, b0.w};
#pragma unroll
            for (int i = 0; i < 4; i++)
#pragma unroll
                for (int j = 0; j < 4; j++) acc[i][j] += ra[i] * rb[j];
        }
        // ssum pass (k ascending, tiles ascending)
        if (tid < 128) {
#pragma unroll
            for (int k = 0; k < BKM; k++) row_sum += Ps[cur][k][tid];
        }
        // store next tile into buffer cur^1
        if (t + 1 < NT) {
            int nxt = cur ^ 1;
            if (tid < 256) {
                int k = tid >> 4, c = (tid & 15) * 4;
                *(float4*)&Ws[nxt][k][c] = wreg;
            }
#pragma unroll
            for (int i = 0; i < 4; i++) {
                int idx = tid + i * 512;
                int r = idx >> 4, kk = idx & 15;
                float s = sreg[i];
                bool mask = (rinvs[r] * s) > 0.0f;
                float e = f1s[r] + g_f2[h * N_NODES + m1 + kk];
                e = e > 0.0f ? e : ALPHA * e;
                Ps[nxt][kk][r] = mask ? __expf(e) : 0.0f;
            }
        }
        __syncthreads();
    }

    if (tid < 128) ssum_s[tid] = row_sum;
    __syncthreads();

#pragma unroll
    for (int i = 0; i < 4; i++) {
        int r = by + ty * 4 + i;
        float sden = ssum_s[ty * 4 + i];
#pragma unroll
        for (int j = 0; j < 4; j++) {
            int c = h * 64 + tx * 4 + j;
            g_x2[(size_t)r * F1 + c] = eluf(acc[i][j] / sden) + g_x1r[(size_t)r * F1 + c];
        }
    }
}

// ---------------- fused flash-GAT single head (split-K=2, double-buffered) ----------------
__global__ void fused_gat_single()
{
    int bx = blockIdx.x * 64;
    int byl = blockIdx.y * 64;
    int by = TOTAL_CATS + byl;
    int z = blockIdx.z;
    int m_base = z * KHALF;
    int tid = threadIdx.x;
    int tx = tid & 15;
    int ty = tid >> 4;

    __shared__ float Ps[2][BKS][68];
    __shared__ float Ws[2][BKS][68];
    __shared__ float f1s[64], rinvs[64];

    if (tid < 64) {
        f1s[tid]   = g_f1o[by + tid];
        rinvs[tid] = g_rinv[by + tid];
    }
    __syncthreads();

    // preload tile 0
    {
#pragma unroll
        for (int i = 0; i < 2; i++) {
            int idx = tid + i * 256;
            int k = idx >> 4, c = (idx & 15) * 4;
            *(float4*)&Ws[0][k][c] =
                *(const float4*)&g_wh2[(size_t)(m_base + k) * ATT_OUT + bx + c];
        }
#pragma unroll
        for (int i = 0; i < 8; i++) {
            int idx = tid + i * 256;
            int r = idx >> 5, k = idx & 31;
            float s = g_sim[(size_t)(by + r) * N_NODES + m_base + k];
            bool mask = (rinvs[r] * s) > 0.0f;
            float e = f1s[r] + g_f2o[m_base + k];
            e = e > 0.0f ? e : ALPHA * e;
            Ps[0][k][r] = mask ? __expf(e) : 0.0f;
        }
    }
    __syncthreads();

    float acc[4][4];
#pragma unroll
    for (int i = 0; i < 4; i++)
#pragma unroll
        for (int j = 0; j < 4; j++) acc[i][j] = 0.0f;
    float row_sum = 0.0f;

    const int NT = KHALF / BKS;    // 72
    for (int t = 0; t < NT; t++) {
        int cur = t & 1;
        int m1 = m_base + (t + 1) * BKS;
        float4 wreg[2];
        float sreg[8];
        if (t + 1 < NT) {
#pragma unroll
            for (int i = 0; i < 2; i++) {
                int idx = tid + i * 256;
                int k = idx >> 4, c = (idx & 15) * 4;
                wreg[i] = *(const float4*)&g_wh2[(size_t)(m1 + k) * ATT_OUT + bx + c];
            }
#pragma unroll
            for (int i = 0; i < 8; i++) {
                int idx = tid + i * 256;
                int r = idx >> 5, k = idx & 31;
                sreg[i] = g_sim[(size_t)(by + r) * N_NODES + m1 + k];
            }
        }
        // compute on buffer cur
#pragma unroll
        for (int kk = 0; kk < BKS; kk++) {
            float4 a0 = *(float4*)&Ps[cur][kk][ty * 4];
            float4 b0 = *(float4*)&Ws[cur][kk][tx * 4];
            float ra[4] = {a0.x, a0.y, a0.z, a0.w};
            float rb[4] = {b0.x, b0.y, b0.z, b0.w};
#pragma unroll
            for (int i = 0; i < 4; i++)
#pragma unroll
                for (int j = 0; j < 4; j++) acc[i][j] += ra[i] * rb[j];
        }
        if (tid < 64) {
#pragma unroll
            for (int k = 0; k < BKS; k++) row_sum += Ps[cur][k][tid];
        }
        // store next tile
        if (t + 1 < NT) {
            int nxt = cur ^ 1;
#pragma unroll
            for (int i = 0; i < 2; i++) {
                int idx = tid + i * 256;
                int k = idx >> 4, c = (idx & 15) * 4;
                *(float4*)&Ws[nxt][k][c] = wreg[i];
            }
#pragma unroll
            for (int i = 0; i < 8; i++) {
                int idx = tid + i * 256;
                int r = idx >> 5, k = idx & 31;
                float s = sreg[i];
                bool mask = (rinvs[r] * s) > 0.0f;
                float e = f1s[r] + g_f2o[m1 + k];
                e = e > 0.0f ? e : ALPHA * e;
                Ps[nxt][k][r] = mask ? __expf(e) : 0.0f;
            }
        }
        __syncthreads();
    }

    float* accout = g_acc1 + (size_t)z * NC * ATT_OUT;
#pragma unroll
    for (int i = 0; i < 4; i++) {
        int rl = byl + ty * 4 + i;
#pragma unroll
        for (int j = 0; j < 4; j++)
            accout[(size_t)rl * ATT_OUT + bx + tx * 4 + j] = acc[i][j];
    }
    if (blockIdx.x == 0 && tid < 64)
        g_ssum1[z * NC + byl + tid] = row_sum;
}

__global__ void combine_single()
{
    int i = blockIdx.x * 256 + threadIdx.x;
    int r = i >> 8;
    int c = i & 255;
    float a = g_acc1[i] + g_acc1[NC * ATT_OUT + i];
    float s = g_ssum1[r] + g_ssum1[NC + r];
    g_x3[i] = eluf(a / s + g_x2[(size_t)(TOTAL_CATS + r) * F1 + c]);
}

// ---------------- bipartite-graph column softmax — LOCKED ----------------
__global__ void bgs_kernel(float* __restrict__ out)
{
    int ds = blockIdx.y;
    int tx = threadIdx.x, ty = threadIdx.y;
    int jloc = blockIdx.x * 32 + tx;
    int col = TOTAL_CATS + jloc;
    int base = ds * NC;
    __shared__ float red[8][33];

    float mx = -3.4e38f;
    for (int i = ty; i < NC; i += 8) {
        float v = (g_rinv[base + i] * g_sim[(size_t)(base + i) * N_NODES + col]) / 0.05f;
        mx = fmaxf(mx, v);
    }
    red[ty][tx] = mx; __syncthreads();
    if (ty == 0) {
        float m = red[0][tx];
        for (int k = 1; k < 8; k++) m = fmaxf(m, red[k][tx]);
        red[0][tx] = m;
    }
    __syncthreads();
    mx = red[0][tx];
    __syncthreads();

    float s = 0.0f;
    for (int i = ty; i < NC; i += 8) {
        float v = (g_rinv[base + i] * g_sim[(size_t)(base + i) * N_NODES + col]) / 0.05f;
        s += __expf(v - mx);
    }
    red[ty][tx] = s; __syncthreads();
    if (ty == 0) {
        float t2 = 0.0f;
        for (int k = 0; k < 8; k++) t2 += red[k][tx];
        red[0][tx] = t2;
    }
    __syncthreads();
    float inv = 1.0f / red[0][tx];

    float* o = out + NC * MLP + (size_t)ds * NC * NC;
    for (int i = ty; i < NC; i += 8) {
        float v = (g_rinv[base + i] * g_sim[(size_t)(base + i) * N_NODES + col]) / 0.05f;
        o[(size_t)i * NC + jloc] = __expf(v - mx) * inv;
    }
}

// ---------------- launch (single stream) ----------------
extern "C" void kernel_launch(void* const* d_in, const int* in_sizes, int n_in,
                              void* d_out, int out_size)
{
    const float* x        = (const float*)d_in[0];
    const float* W_before = (const float*)d_in[1];
    const float* b_before = (const float*)d_in[2];
    const float* W_adj    = (const float*)d_in[3];
    const float* b_adj    = (const float*)d_in[4];
    const float* W_heads  = (const float*)d_in[5];
    const float* a_heads  = (const float*)d_in[6];
    const float* W_out    = (const float*)d_in[7];
    const float* a_out    = (const float*)d_in[8];
    const float* W_lin1   = (const float*)d_in[9];
    const float* b_lin1   = (const float*)d_in[10];
    float* out = (float*)d_out;

    float *p_x1, *p_x1r, *p_naf, *p_whcat, *p_x2, *p_wh2, *p_x3, *p_bcat;
    cudaGetSymbolAddress((void**)&p_x1, g_x1);
    cudaGetSymbolAddress((void**)&p_x1r, g_x1r);
    cudaGetSymbolAddress((void**)&p_naf, g_naf);
    cudaGetSymbolAddress((void**)&p_whcat, g_whcat);
    cudaGetSymbolAddress((void**)&p_x2, g_x2);
    cudaGetSymbolAddress((void**)&p_wh2, g_wh2);
    cudaGetSymbolAddress((void**)&p_x3, g_x3);
    cudaGetSymbolAddress((void**)&p_bcat, g_bcat);

    // 1. x1 = x @ W_before + b_before  (also emits relu(x1) -> g_x1r)
    sgemm<128, 64, 16, 8, 4, 0><<<dim3(F1 / 64, N_NODES / 128), 256>>>(
        x, NFEAT, W_before, F1, p_x1, F1, N_NODES, F1, NFEAT, b_before, p_x1r);

    // 2. af = x1 @ W_adj + b_adj — LOCKED params (reads raw g_x1)
    sgemm<64, 64, 16, 4, 4, 0><<<dim3(1, N_NODES / 64), 256>>>(
        p_x1, F1, W_adj, FADJ, p_naf, FADJ, N_NODES, FADJ, F1, b_adj, nullptr);

    // 3. normalize rows — LOCKED
    norm_rows<<<N_NODES, 64>>>();

    // 4. sim = naf @ naf^T — LOCKED math
    gemm_nt_sim<<<dim3(N_NODES / 64, N_NODES / 64), 256>>>();

    // 5. r_inv — LOCKED math, merged launch
    rowsum_all<<<N_NODES, 256>>>();

    // 6. repack W_heads
    repack_wheads<<<(NHEADS * F1 * DHID + 255) / 256, 256>>>(W_heads);

    // 7. whcat = relu(x1) @ bcat
    sgemm<128, 64, 16, 8, 4, 0><<<dim3(F1 / 64, N_NODES / 128), 256>>>(
        p_x1r, F1, p_bcat, F1, p_whcat, F1, N_NODES, F1, F1, nullptr, nullptr);

    // 8. f1/f2 per head
    f12_mh<<<N_NODES, 128>>>(a_heads);

    // 9. fused multihead attention (512 threads, double-buffered)
    fused_gat_mh<<<dim3(NHEADS, N_NODES / 128), 512>>>();

    // 10. wh2 = x2 @ W_out
    sgemm<128, 64, 16, 8, 4, 0><<<dim3(ATT_OUT / 64, N_NODES / 128), 256>>>(
        p_x2, F1, W_out, ATT_OUT, p_wh2, ATT_OUT, N_NODES, ATT_OUT, F1, nullptr, nullptr);

    // 11. f1o/f2o
    f12_single<<<N_NODES, 256>>>(a_out);

    // 12. fused single-head attention (split-K=2, double-buffered) + combine
    fused_gat_single<<<dim3(ATT_OUT / 64, NC / 64, 2), 256>>>();
    combine_single<<<NC * ATT_OUT / 256, 256>>>();

    // 13. feat_mlp tail = x3 @ W_lin1 + b_lin1
    sgemm<128, 64, 16, 8, 4, 0><<<dim3(MLP / 64, NC / 128), 256>>>(
        p_x3, ATT_OUT, W_lin1, MLP, out, MLP, NC, MLP, ATT_OUT, b_lin1, nullptr);

    // 14. bipartite column softmaxes — LOCKED
    bgs_kernel<<<dim3(NC / 32, 2), dim3(32, 8)>>>(out);
}